// round 6
// baseline (speedup 1.0000x reference)
#include <cuda_runtime.h>
#include <cstdint>

// Batched weighted Kabsch, Horn quaternion + closed-form quartic eigen.
// R3 structure (2-warp CTAs, 32 batches per warp-tile, 1 lane = 1 batch,
// single-buffered cp.async staging, 12 warps/SM) made persistent, plus
// prefetch.global.L2 of each warp's NEXT tile so HBM streams during the
// wait+compute phase and the next cp.async completes at L2 latency.

#define BPW 32                    // batches per warp-tile
#define WARPS 2                   // warps per CTA

__device__ __forceinline__ void cp16(uint32_t dst, const void* src, bool pred) {
    asm volatile(
        "{\n\t.reg .pred p;\n\t"
        "setp.ne.u32 p, %2, 0;\n\t"
        "@p cp.async.cg.shared.global [%0], [%1], 16;\n\t}"
        :: "r"(dst), "l"(src), "r"((int)pred));
}

__device__ __forceinline__ void pfL2(const char* p) {
    asm volatile("prefetch.global.L2 [%0];" :: "l"(p));
}

__device__ __forceinline__ const char* pmin(const char* a, const char* b) {
    return a < b ? a : b;
}

__device__ __forceinline__ void stage_tile(uint32_t sa, uint32_t sb, uint32_t sw,
                                           const float4* __restrict__ A4,
                                           const float4* __restrict__ B4,
                                           const float4* __restrict__ W4,
                                           long tile, int lane, long bs)
{
    long baseA = tile * (BPW * 15);
    long baseW = tile * (BPW * 5);
    long aLim = bs * 15, wLim = bs * 5;
    #pragma unroll
    for (int i = 0; i < 15; i++) {
        int  o = i * 32 + lane;
        long idx = baseA + o;
        bool ok = idx < aLim;
        cp16(sa + o * 16, A4 + idx, ok);
        cp16(sb + o * 16, B4 + idx, ok);
    }
    #pragma unroll
    for (int i = 0; i < 5; i++) {
        int  o = i * 32 + lane;
        long idx = baseW + o;
        cp16(sw + o * 16, W4 + idx, idx < wLim);
    }
}

// Prefetch one whole warp-tile (A:7680B, B:7680B, W:2560B) to L2, one
// 128B line per prefetch, spread across lanes; clamped to array bounds.
__device__ __forceinline__ void prefetch_tile(const float4* __restrict__ A4,
                                              const float4* __restrict__ B4,
                                              const float4* __restrict__ W4,
                                              long tile, int lane, long bs)
{
    const char* aEnd = (const char*)(A4 + bs * 15) - 128;
    const char* bEnd = (const char*)(B4 + bs * 15) - 128;
    const char* wEnd = (const char*)(W4 + bs * 5)  - 128;
    const char* a = (const char*)(A4 + tile * (BPW * 15)) + lane * 128;
    const char* b = (const char*)(B4 + tile * (BPW * 15)) + lane * 128;
    pfL2(pmin(a, aEnd));
    pfL2(pmin(b, bEnd));
    if (lane < 28) {                       // lines 32..59 of 60
        pfL2(pmin(a + 4096, aEnd));
        pfL2(pmin(b + 4096, bEnd));
    }
    if (lane < 20) {                       // 20 lines of W
        const char* w = (const char*)(W4 + tile * (BPW * 5)) + lane * 128;
        pfL2(pmin(w, wEnd));
    }
}

__global__ __launch_bounds__(WARPS * 32)
void kabsch_kernel(const float4* __restrict__ A4,
                   const float4* __restrict__ B4,
                   const float4* __restrict__ W4,
                   float* __restrict__ out, int bs, int nTiles)
{
    __shared__ float4 sA[WARPS][BPW * 15];
    __shared__ float4 sB[WARPS][BPW * 15];
    __shared__ float4 sW[WARPS][BPW * 5];

    const int warp = threadIdx.x >> 5;
    const int lane = threadIdx.x & 31;
    uint32_t sa = (uint32_t)__cvta_generic_to_shared(&sA[warp][0]);
    uint32_t sb = (uint32_t)__cvta_generic_to_shared(&sB[warp][0]);
    uint32_t sw = (uint32_t)__cvta_generic_to_shared(&sW[warp][0]);

    const long wstride = (long)gridDim.x * WARPS;

    for (long t = (long)blockIdx.x * WARPS + warp; t < nTiles; t += wstride) {
        stage_tile(sa, sb, sw, A4, B4, W4, t, lane, bs);
        asm volatile("cp.async.commit_group;" ::: "memory");

        long nt = t + wstride;
        if (nt < nTiles)
            prefetch_tile(A4, B4, W4, nt, lane, bs);

        asm volatile("cp.async.wait_group 0;" ::: "memory");
        __syncwarp();

        const long b = t * BPW + lane;
        if (b < bs) {
            const float4* a4 = &sA[warp][lane * 15];
            const float4* b4 = &sB[warp][lane * 15];
            const float4* w4 = &sW[warp][lane * 5];

            float Sw = 0.f;
            float Sa0 = 0.f, Sa1 = 0.f, Sa2 = 0.f;
            float Sb0 = 0.f, Sb1 = 0.f, Sb2 = 0.f;
            float S00 = 0.f, S01 = 0.f, S02 = 0.f;
            float S10 = 0.f, S11 = 0.f, S12 = 0.f;
            float S20 = 0.f, S21 = 0.f, S22 = 0.f;

            #pragma unroll
            for (int c = 0; c < 5; c++) {
                float4 wv = w4[c];
                float4 A0 = a4[3*c + 0], A1 = a4[3*c + 1], A2 = a4[3*c + 2];
                float4 B0 = b4[3*c + 0], B1 = b4[3*c + 1], B2 = b4[3*c + 2];
                float af[12] = {A0.x, A0.y, A0.z, A0.w, A1.x, A1.y, A1.z, A1.w,
                                A2.x, A2.y, A2.z, A2.w};
                float bf[12] = {B0.x, B0.y, B0.z, B0.w, B1.x, B1.y, B1.z, B1.w,
                                B2.x, B2.y, B2.z, B2.w};
                float wf[4]  = {wv.x, wv.y, wv.z, wv.w};
                #pragma unroll
                for (int p = 0; p < 4; p++) {
                    float w = (wf[p] < 0.0f) ? 0.0f : wf[p];
                    float ax = af[3*p + 0], ay = af[3*p + 1], az = af[3*p + 2];
                    float bx = bf[3*p + 0], by = bf[3*p + 1], bz = bf[3*p + 2];
                    Sw += w;
                    float wax = w * ax, way = w * ay, waz = w * az;
                    Sa0 += wax; Sa1 += way; Sa2 += waz;
                    Sb0 += w * bx; Sb1 += w * by; Sb2 += w * bz;
                    S00 += wax * bx; S01 += wax * by; S02 += wax * bz;
                    S10 += way * bx; S11 += way * by; S12 += way * bz;
                    S20 += waz * bx; S21 += waz * by; S22 += waz * bz;
                }
            }

            const float EPS = 1e-6f;
            float Wp  = Sw + EPS;
            float inv = 1.0f / Wp;
            float factor = (Wp + EPS) * inv * inv;
            S00 -= factor * Sa0 * Sb0; S01 -= factor * Sa0 * Sb1; S02 -= factor * Sa0 * Sb2;
            S10 -= factor * Sa1 * Sb0; S11 -= factor * Sa1 * Sb1; S12 -= factor * Sa1 * Sb2;
            S20 -= factor * Sa2 * Sb0; S21 -= factor * Sa2 * Sb1; S22 -= factor * Sa2 * Sb2;

            float cA0 = Sa0 * inv, cA1 = Sa1 * inv, cA2 = Sa2 * inv;
            float cB0 = Sb0 * inv, cB1 = Sb1 * inv, cB2 = Sb2 * inv;

            float f2 = S00*S00 + S01*S01 + S02*S02
                     + S10*S10 + S11*S11 + S12*S12
                     + S20*S20 + S21*S21 + S22*S22;
            float sc = rsqrtf(f2 + 1e-30f);
            float h00 = S00*sc, h01 = S01*sc, h02 = S02*sc;
            float h10 = S10*sc, h11 = S11*sc, h12 = S12*sc;
            float h20 = S20*sc, h21 = S21*sc, h22 = S22*sc;

            float c00 =  (h11*h22 - h12*h21);
            float c01 = -(h10*h22 - h12*h20);
            float c02 =  (h10*h21 - h11*h20);
            float c10 = -(h01*h22 - h02*h21);
            float c11 =  (h00*h22 - h02*h20);
            float c12 = -(h00*h21 - h01*h20);
            float c20 =  (h01*h12 - h02*h11);
            float c21 = -(h00*h12 - h02*h10);
            float c22 =  (h00*h11 - h01*h10);
            float detH = h00*c00 + h01*c01 + h02*c02;
            float cof2 = c00*c00 + c01*c01 + c02*c02
                       + c10*c10 + c11*c11 + c12*c12
                       + c20*c20 + c21*c21 + c22*c22;
            float fn = (f2 + 1e-30f) * sc * sc;

            float C2 = -2.0f * fn;
            float C1 = -8.0f * detH;
            float C0 = fn * fn - 4.0f * cof2;
            float lam = 1.7320508f;
            #pragma unroll
            for (int it = 0; it < 12; it++) {
                float l2 = lam * lam;
                float fv = ((l2 + C2) * lam + C1) * lam + C0;
                float fp = (4.0f * l2 + 2.0f * C2) * lam + C1;
                lam -= __fdividef(fv, fp);
            }

            float m00 = (h00 + h11 + h22) - lam;
            float m01 = h12 - h21;
            float m02 = h20 - h02;
            float m03 = h01 - h10;
            float m11 = (h00 - h11 - h22) - lam;
            float m12 = h01 + h10;
            float m13 = h20 + h02;
            float m22 = (h11 - h00 - h22) - lam;
            float m23 = h12 + h21;
            float m33 = (h22 - h00 - h11) - lam;

            #define DET3(a,b,c,d,e,f,g,h,i) ((a)*((e)*(i)-(f)*(h)) - (b)*((d)*(i)-(f)*(g)) + (c)*((d)*(h)-(e)*(g)))
            float A00 =  DET3(m11,m12,m13, m12,m22,m23, m13,m23,m33);
            float A11 =  DET3(m00,m02,m03, m02,m22,m23, m03,m23,m33);
            float A22 =  DET3(m00,m01,m03, m01,m11,m13, m03,m13,m33);
            float A33 =  DET3(m00,m01,m02, m01,m11,m12, m02,m12,m22);
            float A01 = -DET3(m01,m12,m13, m02,m22,m23, m03,m23,m33);
            float A02 =  DET3(m01,m11,m13, m02,m12,m23, m03,m13,m33);
            float A03 = -DET3(m01,m11,m12, m02,m12,m22, m03,m13,m23);
            float A12 = -DET3(m00,m01,m03, m02,m12,m23, m03,m13,m33);
            float A13 =  DET3(m00,m01,m02, m02,m12,m22, m03,m13,m23);
            float A23 = -DET3(m00,m01,m02, m01,m11,m12, m03,m13,m23);
            #undef DET3

            float best = fabsf(A00);
            float q0 = A00, qx = A01, qy = A02, qz = A03;
            float d1 = fabsf(A11);
            if (d1 > best) { best = d1; q0 = A01; qx = A11; qy = A12; qz = A13; }
            float d2 = fabsf(A22);
            if (d2 > best) { best = d2; q0 = A02; qx = A12; qy = A22; qz = A23; }
            float d3 = fabsf(A33);
            if (d3 > best) { best = d3; q0 = A03; qx = A13; qy = A23; qz = A33; }

            float qn = rsqrtf(q0*q0 + qx*qx + qy*qy + qz*qz + 1e-30f);
            q0 *= qn; qx *= qn; qy *= qn; qz *= qn;

            float xx = qx*qx, yy = qy*qy, zz = qz*qz;
            float xy = qx*qy, xz = qx*qz, yz = qy*qz;
            float wx = q0*qx, wy = q0*qy, wz = q0*qz;
            float r00 = 1.0f - 2.0f*(yy + zz);
            float r01 = 2.0f*(xy - wz);
            float r02 = 2.0f*(xz + wy);
            float r10 = 2.0f*(xy + wz);
            float r11 = 1.0f - 2.0f*(xx + zz);
            float r12 = 2.0f*(yz - wx);
            float r20 = 2.0f*(xz - wy);
            float r21 = 2.0f*(yz + wx);
            float r22 = 1.0f - 2.0f*(xx + yy);

            float t0 = cB0 - (r00*cA0 + r01*cA1 + r02*cA2);
            float t1 = cB1 - (r10*cA0 + r11*cA1 + r12*cA2);
            float t2 = cB2 - (r20*cA0 + r21*cA1 + r22*cA2);

            float4* o = reinterpret_cast<float4*>(out) + b * 4;
            o[0] = make_float4(r00, r01, r02, t0);
            o[1] = make_float4(r10, r11, r12, t1);
            o[2] = make_float4(r20, r21, r22, t2);
            o[3] = make_float4(0.0f, 0.0f, 0.0f, 1.0f);
        }
        __syncwarp();   // buffer free before next stage_tile overwrites it
    }
}

extern "C" void kernel_launch(void* const* d_in, const int* in_sizes, int n_in,
                              void* d_out, int out_size)
{
    const float4* A = (const float4*)d_in[0];
    const float4* B = (const float4*)d_in[1];
    const float4* W = (const float4*)d_in[2];
    int bs = in_sizes[2] / 20;            // weights: [bs, 20]
    int nTiles = (bs + BPW - 1) / BPW;
    int grid = 6 * 148;                   // 6 CTAs/SM (35.8KB smem) = 12 warps/SM
    int maxg = (nTiles + WARPS - 1) / WARPS;
    if (grid > maxg) grid = maxg;
    kabsch_kernel<<<grid, WARPS * 32>>>(A, B, W, (float*)d_out, bs, nTiles);
}

// round 7
// speedup vs baseline: 1.0932x; 1.0932x over previous
#include <cuda_runtime.h>
#include <cstdint>

// Batched weighted Kabsch, Horn quaternion + closed-form quartic eigen.
// R3 structure (one-shot 2-warp CTAs, 32 batches per warp-tile, 1 lane = 1
// batch), but staging via cp.async.bulk: 3 bulk copies per warp-tile instead
// of 1120 x 16B cp.async ops — removes the LSU issue bottleneck.

#define BPW 32                    // batches per warp-tile

__global__ __launch_bounds__(64)
void kabsch_kernel(const float4* __restrict__ A4,
                   const float4* __restrict__ B4,
                   const float4* __restrict__ W4,
                   float* __restrict__ out, int bs)
{
    __shared__ float4 sA[2][BPW * 15];
    __shared__ float4 sB[2][BPW * 15];
    __shared__ float4 sW[2][BPW * 5];
    __shared__ alignas(8) unsigned long long mbar[2];

    const int warp = threadIdx.x >> 5;
    const int lane = threadIdx.x & 31;
    const long tile = (long)blockIdx.x * 2 + warp;
    const long b0   = tile * BPW;                 // first batch of this tile
    if (b0 >= bs) return;

    const int nb = (int)((bs - b0) < BPW ? (bs - b0) : BPW);  // batches staged

    uint32_t sa = (uint32_t)__cvta_generic_to_shared(&sA[warp][0]);
    uint32_t sb = (uint32_t)__cvta_generic_to_shared(&sB[warp][0]);
    uint32_t sw = (uint32_t)__cvta_generic_to_shared(&sW[warp][0]);
    uint32_t mb = (uint32_t)__cvta_generic_to_shared(&mbar[warp]);

    if (lane == 0) {
        asm volatile("mbarrier.init.shared.b64 [%0], 1;" :: "r"(mb) : "memory");
        // Make init visible to the async proxy before bulk-copy complete_tx.
        asm volatile("fence.proxy.async.shared::cta;" ::: "memory");

        const uint32_t abBytes = (uint32_t)nb * 240u;   // 15 float4 per batch
        const uint32_t wBytes  = (uint32_t)nb * 80u;    // 5 float4 per batch
        asm volatile("mbarrier.arrive.expect_tx.shared.b64 _, [%0], %1;"
                     :: "r"(mb), "r"(2u * abBytes + wBytes) : "memory");
        asm volatile("cp.async.bulk.shared::cta.global.mbarrier::complete_tx::bytes"
                     " [%0], [%1], %2, [%3];"
                     :: "r"(sa), "l"(A4 + b0 * 15), "r"(abBytes), "r"(mb) : "memory");
        asm volatile("cp.async.bulk.shared::cta.global.mbarrier::complete_tx::bytes"
                     " [%0], [%1], %2, [%3];"
                     :: "r"(sb), "l"(B4 + b0 * 15), "r"(abBytes), "r"(mb) : "memory");
        asm volatile("cp.async.bulk.shared::cta.global.mbarrier::complete_tx::bytes"
                     " [%0], [%1], %2, [%3];"
                     :: "r"(sw), "l"(W4 + b0 * 5), "r"(wBytes), "r"(mb) : "memory");
    }
    __syncwarp();

    // Wait for the tile (phase 0, one-shot).
    {
        uint32_t done;
        asm volatile(
            "{\n\t.reg .pred p;\n\t"
            "mbarrier.try_wait.parity.acquire.cta.shared::cta.b64 p, [%1], 0;\n\t"
            "selp.b32 %0, 1, 0, p;\n\t}"
            : "=r"(done) : "r"(mb) : "memory");
        if (!done) {
            asm volatile(
                "{\n\t.reg .pred P1;\n\t"
                "WAIT_LOOP_%=:\n\t"
                "mbarrier.try_wait.parity.acquire.cta.shared::cta.b64 P1, [%0], 0, 0x989680;\n\t"
                "@P1 bra.uni WAIT_DONE_%=;\n\t"
                "bra.uni WAIT_LOOP_%=;\n\t"
                "WAIT_DONE_%=:\n\t}"
                :: "r"(mb) : "memory");
        }
    }
    __syncwarp();

    if (lane >= nb) return;
    const long b = b0 + lane;

    const float4* a4 = &sA[warp][lane * 15];
    const float4* b4 = &sB[warp][lane * 15];
    const float4* w4 = &sW[warp][lane * 5];

    float Sw = 0.f;
    float Sa0 = 0.f, Sa1 = 0.f, Sa2 = 0.f;
    float Sb0 = 0.f, Sb1 = 0.f, Sb2 = 0.f;
    float S00 = 0.f, S01 = 0.f, S02 = 0.f;
    float S10 = 0.f, S11 = 0.f, S12 = 0.f;
    float S20 = 0.f, S21 = 0.f, S22 = 0.f;

    #pragma unroll
    for (int c = 0; c < 5; c++) {
        float4 wv = w4[c];
        float4 A0 = a4[3*c + 0], A1 = a4[3*c + 1], A2 = a4[3*c + 2];
        float4 B0 = b4[3*c + 0], B1 = b4[3*c + 1], B2 = b4[3*c + 2];
        float af[12] = {A0.x, A0.y, A0.z, A0.w, A1.x, A1.y, A1.z, A1.w,
                        A2.x, A2.y, A2.z, A2.w};
        float bf[12] = {B0.x, B0.y, B0.z, B0.w, B1.x, B1.y, B1.z, B1.w,
                        B2.x, B2.y, B2.z, B2.w};
        float wf[4]  = {wv.x, wv.y, wv.z, wv.w};
        #pragma unroll
        for (int p = 0; p < 4; p++) {
            float w = (wf[p] < 0.0f) ? 0.0f : wf[p];
            float ax = af[3*p + 0], ay = af[3*p + 1], az = af[3*p + 2];
            float bx = bf[3*p + 0], by = bf[3*p + 1], bz = bf[3*p + 2];
            Sw += w;
            float wax = w * ax, way = w * ay, waz = w * az;
            Sa0 += wax; Sa1 += way; Sa2 += waz;
            Sb0 += w * bx; Sb1 += w * by; Sb2 += w * bz;
            S00 += wax * bx; S01 += wax * by; S02 += wax * bz;
            S10 += way * bx; S11 += way * by; S12 += way * bz;
            S20 += waz * bx; S21 += waz * by; S22 += waz * bz;
        }
    }

    const float EPS = 1e-6f;
    float Wp  = Sw + EPS;
    float inv = 1.0f / Wp;
    float factor = (Wp + EPS) * inv * inv;
    S00 -= factor * Sa0 * Sb0; S01 -= factor * Sa0 * Sb1; S02 -= factor * Sa0 * Sb2;
    S10 -= factor * Sa1 * Sb0; S11 -= factor * Sa1 * Sb1; S12 -= factor * Sa1 * Sb2;
    S20 -= factor * Sa2 * Sb0; S21 -= factor * Sa2 * Sb1; S22 -= factor * Sa2 * Sb2;

    float cA0 = Sa0 * inv, cA1 = Sa1 * inv, cA2 = Sa2 * inv;
    float cB0 = Sb0 * inv, cB1 = Sb1 * inv, cB2 = Sb2 * inv;

    float f2 = S00*S00 + S01*S01 + S02*S02
             + S10*S10 + S11*S11 + S12*S12
             + S20*S20 + S21*S21 + S22*S22;
    float sc = rsqrtf(f2 + 1e-30f);
    float h00 = S00*sc, h01 = S01*sc, h02 = S02*sc;
    float h10 = S10*sc, h11 = S11*sc, h12 = S12*sc;
    float h20 = S20*sc, h21 = S21*sc, h22 = S22*sc;

    float c00 =  (h11*h22 - h12*h21);
    float c01 = -(h10*h22 - h12*h20);
    float c02 =  (h10*h21 - h11*h20);
    float c10 = -(h01*h22 - h02*h21);
    float c11 =  (h00*h22 - h02*h20);
    float c12 = -(h00*h21 - h01*h20);
    float c20 =  (h01*h12 - h02*h11);
    float c21 = -(h00*h12 - h02*h10);
    float c22 =  (h00*h11 - h01*h10);
    float detH = h00*c00 + h01*c01 + h02*c02;
    float cof2 = c00*c00 + c01*c01 + c02*c02
               + c10*c10 + c11*c11 + c12*c12
               + c20*c20 + c21*c21 + c22*c22;
    float fn = (f2 + 1e-30f) * sc * sc;

    float C2 = -2.0f * fn;
    float C1 = -8.0f * detH;
    float C0 = fn * fn - 4.0f * cof2;
    float lam = 1.7320508f;
    #pragma unroll
    for (int it = 0; it < 12; it++) {
        float l2 = lam * lam;
        float fv = ((l2 + C2) * lam + C1) * lam + C0;
        float fp = (4.0f * l2 + 2.0f * C2) * lam + C1;
        lam -= __fdividef(fv, fp);
    }

    float m00 = (h00 + h11 + h22) - lam;
    float m01 = h12 - h21;
    float m02 = h20 - h02;
    float m03 = h01 - h10;
    float m11 = (h00 - h11 - h22) - lam;
    float m12 = h01 + h10;
    float m13 = h20 + h02;
    float m22 = (h11 - h00 - h22) - lam;
    float m23 = h12 + h21;
    float m33 = (h22 - h00 - h11) - lam;

    #define DET3(a,b,c,d,e,f,g,h,i) ((a)*((e)*(i)-(f)*(h)) - (b)*((d)*(i)-(f)*(g)) + (c)*((d)*(h)-(e)*(g)))
    float A00 =  DET3(m11,m12,m13, m12,m22,m23, m13,m23,m33);
    float A11 =  DET3(m00,m02,m03, m02,m22,m23, m03,m23,m33);
    float A22 =  DET3(m00,m01,m03, m01,m11,m13, m03,m13,m33);
    float A33 =  DET3(m00,m01,m02, m01,m11,m12, m02,m12,m22);
    float A01 = -DET3(m01,m12,m13, m02,m22,m23, m03,m23,m33);
    float A02 =  DET3(m01,m11,m13, m02,m12,m23, m03,m13,m33);
    float A03 = -DET3(m01,m11,m12, m02,m12,m22, m03,m13,m23);
    float A12 = -DET3(m00,m01,m03, m02,m12,m23, m03,m13,m33);
    float A13 =  DET3(m00,m01,m02, m02,m12,m22, m03,m13,m23);
    float A23 = -DET3(m00,m01,m02, m01,m11,m12, m03,m13,m23);
    #undef DET3

    float best = fabsf(A00);
    float q0 = A00, qx = A01, qy = A02, qz = A03;
    float d1 = fabsf(A11);
    if (d1 > best) { best = d1; q0 = A01; qx = A11; qy = A12; qz = A13; }
    float d2 = fabsf(A22);
    if (d2 > best) { best = d2; q0 = A02; qx = A12; qy = A22; qz = A23; }
    float d3 = fabsf(A33);
    if (d3 > best) { best = d3; q0 = A03; qx = A13; qy = A23; qz = A33; }

    float qn = rsqrtf(q0*q0 + qx*qx + qy*qy + qz*qz + 1e-30f);
    q0 *= qn; qx *= qn; qy *= qn; qz *= qn;

    float xx = qx*qx, yy = qy*qy, zz = qz*qz;
    float xy = qx*qy, xz = qx*qz, yz = qy*qz;
    float wx = q0*qx, wy = q0*qy, wz = q0*qz;
    float r00 = 1.0f - 2.0f*(yy + zz);
    float r01 = 2.0f*(xy - wz);
    float r02 = 2.0f*(xz + wy);
    float r10 = 2.0f*(xy + wz);
    float r11 = 1.0f - 2.0f*(xx + zz);
    float r12 = 2.0f*(yz - wx);
    float r20 = 2.0f*(xz - wy);
    float r21 = 2.0f*(yz + wx);
    float r22 = 1.0f - 2.0f*(xx + yy);

    float t0 = cB0 - (r00*cA0 + r01*cA1 + r02*cA2);
    float t1 = cB1 - (r10*cA0 + r11*cA1 + r12*cA2);
    float t2 = cB2 - (r20*cA0 + r21*cA1 + r22*cA2);

    float4* o = reinterpret_cast<float4*>(out) + b * 4;
    o[0] = make_float4(r00, r01, r02, t0);
    o[1] = make_float4(r10, r11, r12, t1);
    o[2] = make_float4(r20, r21, r22, t2);
    o[3] = make_float4(0.0f, 0.0f, 0.0f, 1.0f);
}

extern "C" void kernel_launch(void* const* d_in, const int* in_sizes, int n_in,
                              void* d_out, int out_size)
{
    const float4* A = (const float4*)d_in[0];
    const float4* B = (const float4*)d_in[1];
    const float4* W = (const float4*)d_in[2];
    int bs = in_sizes[2] / 20;                      // weights: [bs, 20]
    int nTiles = (bs + BPW - 1) / BPW;
    int blocks = (nTiles + 1) / 2;                  // 2 warp-tiles per CTA
    kabsch_kernel<<<blocks, 64>>>(A, B, W, (float*)d_out, bs);
}